// round 16
// baseline (speedup 1.0000x reference)
#include <cuda_runtime.h>
#include <cuda_fp16.h>
#include <cstdint>
#include <math.h>

#define NN 50000
#define KK 16
#define EE 800000
#define BBATCH 1024
#define MAXM 48
#define FD 9
#define AD 10
#define HH 64
#define NEGINF (-1e9f)
#define NB_G 196                 // ceil((NN+1)/256)

__device__ __forceinline__ unsigned pack_half2(float a, float b) {
    __half2 h = __floats2half2_rn(a, b);
    return *reinterpret_cast<unsigned*>(&h);
}
__device__ __forceinline__ float2 unpack_half2(unsigned u) {
    __half2 h = *reinterpret_cast<__half2*>(&u);
    return __half22float2(h);
}

// ---------------- scratch ------------------------------------------------------
__device__ uint2  d_th1h[(NN + 1) * 16];   // fp16 hp1 @ Wg
__device__ uint2  d_tm1h[(NN + 1) * 16];   // fp16 hp1 @ Wm
__device__ uint2  d_hp2h[(NN + 1) * 16];   // fp16 hp2
__device__ float d_gp0[NN + 1];
__device__ float d_gp1[NN + 1];
__device__ float d_gm1[NN + 1];
__device__ float d_a9s[NN * 10];           // 9 aggregated tf feats + s
__device__ float d_accX16[NN * 16];
__device__ float4 d_p4[16];
__device__ float4 d_q4[16];
__device__ float d_qd[AD];
__device__ float d_c;
__device__ float d_wep[FD];      // We @ p
__device__ float d_c0;           // be . p
__device__ float4 d_M14[AD * 16];  // Wd @ Wm
__device__ float4 d_bm4[16];       // bd @ Wm
__device__ float4 d_G94[FD * 16];  // We @ Wg
__device__ float4 d_gb4[16];       // be @ Wg

// ---------------- constants (9 blocks) ------------------------------------------
__global__ __launch_bounds__(256) void k_consts(const float* __restrict__ Wg,
                                                const float* __restrict__ Wm,
                                                const float* __restrict__ a,
                                                const float* __restrict__ Wd,
                                                const float* __restrict__ bd,
                                                const float* __restrict__ We,
                                                const float* __restrict__ be) {
    int t = threadIdx.x;
    int b = blockIdx.x;
    if (b == 0) {
        __shared__ float sp[HH], sq[HH];
        if (t < HH) {
            float p = 0.f, q = 0.f;
            #pragma unroll 8
            for (int i = 0; i < HH; i++) {
                p += Wg[t * HH + i] * a[i];
                q += Wm[t * HH + i] * a[HH + i];
            }
            sp[t] = p; sq[t] = q;
            ((float*)d_p4)[t] = p;
            ((float*)d_q4)[t] = q;
        }
        __syncthreads();
        if (t < AD) {
            float s = 0.f;
            for (int i = 0; i < HH; i++) s += Wd[t * HH + i] * sq[i];
            d_qd[t] = s;
        } else if (t == AD) {
            float s = 0.f;
            for (int i = 0; i < HH; i++) s += bd[i] * sq[i];
            d_c = s;
        } else if (t >= 32 && t < 32 + FD) {
            int r = t - 32;
            float s = 0.f;
            for (int j = 0; j < HH; j++) s += We[r * HH + j] * sp[j];
            d_wep[r] = s;
        } else if (t == 32 + FD) {
            float s = 0.f;
            for (int j = 0; j < HH; j++) s += be[j] * sp[j];
            d_c0 = s;
        }
        if (t < HH) {
            float s = 0.f;
            for (int i = 0; i < HH; i++) s += bd[i] * Wm[i * HH + t];
            ((float*)d_bm4)[t] = s;
        }
    } else if (b <= 4) {
        int idx = (b - 1) * 160 + t;
        if (t < 160 && idx < AD * HH) {
            int r = idx >> 6, j = idx & 63;
            float s = 0.f;
            #pragma unroll 8
            for (int i = 0; i < HH; i++) s += Wd[r * HH + i] * Wm[i * HH + j];
            ((float*)d_M14)[idx] = s;
        }
    } else {
        // blocks 5-8: G9 (576) + gb (64)
        int idx = (b - 5) * 160 + t;
        if (t < 160 && idx < FD * HH + HH) {
            if (idx < FD * HH) {
                int r = idx >> 6, j = idx & 63;
                float s = 0.f;
                #pragma unroll 8
                for (int i = 0; i < HH; i++) s += We[r * HH + i] * Wg[i * HH + j];
                ((float*)d_G94)[idx] = s;
            } else {
                int j = idx - FD * HH;
                float s = 0.f;
                #pragma unroll 8
                for (int i = 0; i < HH; i++) s += be[i] * Wg[i * HH + j];
                ((float*)d_gb4)[j] = s;
            }
        }
    }
}

// ---------------- gp0 only (elog now inline in gather1) ---------------------------
__global__ __launch_bounds__(256) void k_pre(const float* __restrict__ tf) {
    int row = blockIdx.x * 256 + threadIdx.x;
    if (row > NN) return;
    float g = 0.f;
    if (row > 0) {
        const float* r = tf + (row - 1) * FD;
        g = d_c0;
        #pragma unroll
        for (int tt = 0; tt < FD; tt++) g += __ldg(r + tt) * d_wep[tt];
    }
    d_gp0[row] = g;
}

// ---------------- softmax helper (width 16) --------------------------------------
__device__ __forceinline__ float softmax16(float logit) {
    float mx = logit;
    #pragma unroll
    for (int m = 8; m; m >>= 1) mx = fmaxf(mx, __shfl_xor_sync(0xffffffffu, mx, m, 16));
    float ex = __expf(logit - mx);
    float sum = ex;
    #pragma unroll
    for (int m = 8; m; m >>= 1) sum += __shfl_xor_sync(0xffffffffu, sum, m, 16);
    return ex / sum;
}

// ---------------- fused alpha(+elog) + gather, iteration 1 ------------------------
__global__ __launch_bounds__(256) void k_gather1(const int* __restrict__ se,
                                                 const int* __restrict__ bs,
                                                 const float* __restrict__ tf,
                                                 const float* __restrict__ fdg,
                                                 const float* __restrict__ rij) {
    __shared__ float4 sbc[8][2][17];
    int t = threadIdx.x, w = t >> 5, l = t & 31, sub = l & 15, half = l >> 4;
    int n = (blockIdx.x * 8 + w) * 2 + half;     // < NN exactly

    int idx = se[n * KK + sub];
    int e   = bs[n * KK + sub];
    // inline per-edge logit: elog = c + fdg[e].qd[0:9] + rij[e]*qd[9]
    float el = d_c + __ldg(&rij[e]) * d_qd[9];
    {
        const float* xr = fdg + (long)e * FD;
        #pragma unroll
        for (int r = 0; r < FD; r++) el += __ldg(xr + r) * d_qd[r];
    }
    float v = __ldg(&d_gp0[idx]) + el;
    v = (v > 0.f) ? v : 0.2f * v;
    float alpha = softmax16((idx == 0) ? NEGINF : v);

    float sflag = (idx != 0) ? alpha : 0.f;
    #pragma unroll
    for (int m = 8; m; m >>= 1) sflag += __shfl_xor_sync(0xffffffffu, sflag, m, 16);

    sbc[w][half][sub] = make_float4(alpha, __int_as_float(idx), __int_as_float(e), 0.f);
    __syncwarp();

    float a9 = 0.f, ax = 0.f;
    #pragma unroll
    for (int k = 0; k < KK; k++) {
        float4 b = sbc[w][half][k];
        int i  = __float_as_int(b.y);
        int ee = __float_as_int(b.z);
        if (sub < FD) {
            if (i > 0) a9 += b.x * __ldg(&tf[(long)(i - 1) * FD + sub]);
            ax += b.x * __ldg(&fdg[(long)ee * FD + sub]);
        } else if (sub == FD) {
            ax += b.x * __ldg(&rij[ee]);
        }
    }
    if (sub < FD) d_a9s[n * 10 + sub] = a9;
    else if (sub == FD) d_a9s[n * 10 + FD] = sflag;
    d_accX16[n * 16 + sub] = ax;
}

#define FMA4(o, a, w0, w1, w2, w3)                                     \
    o.x += a.x * w0.x + a.y * w1.x + a.z * w2.x + a.w * w3.x;          \
    o.y += a.x * w0.y + a.y * w1.y + a.z * w2.y + a.w * w3.y;          \
    o.z += a.x * w0.z + a.y * w1.z + a.z * w2.z + a.w * w3.z;          \
    o.w += a.x * w0.w + a.y * w1.w + a.z * w2.w + a.w * w3.w;

#define ELU4(o) \
    o.x = (o.x > 0.f) ? o.x : expm1f(o.x); \
    o.y = (o.y > 0.f) ? o.y : expm1f(o.y); \
    o.z = (o.z > 0.f) ? o.z : expm1f(o.z); \
    o.w = (o.w > 0.f) ? o.w : expm1f(o.w);

#define RANK1(o0, o1, o2, o3, m, x0, x1, x2, x3)                       \
    o0.x += x0 * m.x; o0.y += x0 * m.y; o0.z += x0 * m.z; o0.w += x0 * m.w; \
    o1.x += x1 * m.x; o1.y += x1 * m.y; o1.z += x1 * m.z; o1.w += x1 * m.w; \
    o2.x += x2 * m.x; o2.y += x2 * m.y; o2.z += x2 * m.z; o2.w += x2 * m.w; \
    o3.x += x3 * m.x; o3.y += x3 * m.y; o3.z += x3 * m.z; o3.w += x3 * m.w;

// ---------------- mega: hp1 = ELU(a9@G9 + s*gb + accX@M1 + bm);
//                  th1 = hp1@Wg; tm1 = hp1@Wm (fused, fp16 out); gp1/gm1 ---------
// dyn smem: sWg 16K + sWm 16K + sacc 17K + sa9 2.5K + sax 2.5K = 54 KiB (4 blk/SM)
__global__ __launch_bounds__(256, 4) void k_mega(const float* __restrict__ Wg,
                                                 const float* __restrict__ Wm) {
    extern __shared__ float4 dyn[];
    float4* sWg = dyn;                       // 1024 float4
    float4* sWm = dyn + 1024;                // 1024 float4
    float*  sacc = (float*)(dyn + 2048);     // 64*68 (hp1)
    float*  sa9  = sacc + 64 * 68;           // 64*10
    float*  sax  = sa9 + 64 * 10;            // 64*10

    int t = threadIdx.x;
    int nb0 = blockIdx.x * 64;
    for (int i = t; i < HH * 16; i += 256) {
        sWg[i] = ((const float4*)Wg)[i];
        sWm[i] = ((const float4*)Wm)[i];
    }
    for (int i = t; i < 640; i += 256) {
        int node = i / 10, r = i % 10, n = nb0 + node;
        sa9[i] = (n < NN) ? d_a9s[n * 10 + r] : 0.f;
        sax[i] = (n < NN) ? d_accX16[n * 16 + r] : 0.f;
    }
    __syncthreads();

    int ch = t & 15, g = t >> 4;
    int nl = g * 4;

    // ---- pass 1: hp1 = ELU(a9@G9 + s*gb + accX@M1 + bm) ----
    float4 bm = __ldg(&d_bm4[ch]);
    float4 o0 = bm, o1 = bm, o2 = bm, o3 = bm;
    {
        float4 gb = __ldg(&d_gb4[ch]);
        float s0 = sa9[(nl + 0) * 10 + FD], s1 = sa9[(nl + 1) * 10 + FD];
        float s2 = sa9[(nl + 2) * 10 + FD], s3 = sa9[(nl + 3) * 10 + FD];
        RANK1(o0, o1, o2, o3, gb, s0, s1, s2, s3)
    }
    #pragma unroll
    for (int r = 0; r < FD; r++) {
        float4 m = __ldg(&d_G94[r * 16 + ch]);
        float x0 = sa9[(nl + 0) * 10 + r], x1 = sa9[(nl + 1) * 10 + r];
        float x2 = sa9[(nl + 2) * 10 + r], x3 = sa9[(nl + 3) * 10 + r];
        RANK1(o0, o1, o2, o3, m, x0, x1, x2, x3)
    }
    #pragma unroll
    for (int r = 0; r < AD; r++) {
        float4 m = __ldg(&d_M14[r * 16 + ch]);
        float x0 = sax[(nl + 0) * 10 + r], x1 = sax[(nl + 1) * 10 + r];
        float x2 = sax[(nl + 2) * 10 + r], x3 = sax[(nl + 3) * 10 + r];
        RANK1(o0, o1, o2, o3, m, x0, x1, x2, x3)
    }
    ELU4(o0) ELU4(o1) ELU4(o2) ELU4(o3)

    // gp1/gm1 scalars
    {
        float4 p = __ldg(&d_p4[ch]), q = __ldg(&d_q4[ch]);
        float pp0 = o0.x*p.x + o0.y*p.y + o0.z*p.z + o0.w*p.w;
        float pp1 = o1.x*p.x + o1.y*p.y + o1.z*p.z + o1.w*p.w;
        float pp2 = o2.x*p.x + o2.y*p.y + o2.z*p.z + o2.w*p.w;
        float pp3 = o3.x*p.x + o3.y*p.y + o3.z*p.z + o3.w*p.w;
        float qq0 = o0.x*q.x + o0.y*q.y + o0.z*q.z + o0.w*q.w;
        float qq1 = o1.x*q.x + o1.y*q.y + o1.z*q.z + o1.w*q.w;
        float qq2 = o2.x*q.x + o2.y*q.y + o2.z*q.z + o2.w*q.w;
        float qq3 = o3.x*q.x + o3.y*q.y + o3.z*q.z + o3.w*q.w;
        #pragma unroll
        for (int m = 8; m; m >>= 1) {
            pp0 += __shfl_xor_sync(0xffffffffu, pp0, m, 16);
            pp1 += __shfl_xor_sync(0xffffffffu, pp1, m, 16);
            pp2 += __shfl_xor_sync(0xffffffffu, pp2, m, 16);
            pp3 += __shfl_xor_sync(0xffffffffu, pp3, m, 16);
            qq0 += __shfl_xor_sync(0xffffffffu, qq0, m, 16);
            qq1 += __shfl_xor_sync(0xffffffffu, qq1, m, 16);
            qq2 += __shfl_xor_sync(0xffffffffu, qq2, m, 16);
            qq3 += __shfl_xor_sync(0xffffffffu, qq3, m, 16);
        }
        if (ch == 0) {
            if (nb0 + nl + 0 < NN) { d_gp1[nb0 + nl + 1] = pp0; d_gm1[nb0 + nl + 1] = qq0; }
            if (nb0 + nl + 1 < NN) { d_gp1[nb0 + nl + 2] = pp1; d_gm1[nb0 + nl + 2] = qq1; }
            if (nb0 + nl + 2 < NN) { d_gp1[nb0 + nl + 3] = pp2; d_gm1[nb0 + nl + 3] = qq2; }
            if (nb0 + nl + 3 < NN) { d_gp1[nb0 + nl + 4] = pp3; d_gm1[nb0 + nl + 4] = qq3; }
        }
    }

    // write hp1 into own sacc rows — half-warp private, warp sync suffices
    __syncwarp();
    *(float4*)&sacc[(nl + 0) * 68 + ch * 4] = o0;
    *(float4*)&sacc[(nl + 1) * 68 + ch * 4] = o1;
    *(float4*)&sacc[(nl + 2) * 68 + ch * 4] = o2;
    *(float4*)&sacc[(nl + 3) * 68 + ch * 4] = o3;
    __syncwarp();

    // ---- fused passes 2+3: th1 = hp1@Wg, tm1 = hp1@Wm ----
    float4 uA0 = make_float4(0.f,0.f,0.f,0.f), uA1 = uA0, uA2 = uA0, uA3 = uA0;
    float4 uB0 = uA0, uB1 = uA0, uB2 = uA0, uB3 = uA0;
    #pragma unroll
    for (int s4 = 0; s4 < 16; s4++) {
        float4 a0 = *(float4*)&sacc[(nl + 0) * 68 + s4 * 4];
        float4 a1 = *(float4*)&sacc[(nl + 1) * 68 + s4 * 4];
        float4 a2 = *(float4*)&sacc[(nl + 2) * 68 + s4 * 4];
        float4 a3 = *(float4*)&sacc[(nl + 3) * 68 + s4 * 4];
        {
            float4 w0 = sWg[(4 * s4 + 0) * 16 + ch];
            float4 w1 = sWg[(4 * s4 + 1) * 16 + ch];
            float4 w2 = sWg[(4 * s4 + 2) * 16 + ch];
            float4 w3 = sWg[(4 * s4 + 3) * 16 + ch];
            FMA4(uA0, a0, w0, w1, w2, w3)
            FMA4(uA1, a1, w0, w1, w2, w3)
            FMA4(uA2, a2, w0, w1, w2, w3)
            FMA4(uA3, a3, w0, w1, w2, w3)
        }
        {
            float4 w0 = sWm[(4 * s4 + 0) * 16 + ch];
            float4 w1 = sWm[(4 * s4 + 1) * 16 + ch];
            float4 w2 = sWm[(4 * s4 + 2) * 16 + ch];
            float4 w3 = sWm[(4 * s4 + 3) * 16 + ch];
            FMA4(uB0, a0, w0, w1, w2, w3)
            FMA4(uB1, a1, w0, w1, w2, w3)
            FMA4(uB2, a2, w0, w1, w2, w3)
            FMA4(uB3, a3, w0, w1, w2, w3)
        }
    }
    #pragma unroll
    for (int m = 0; m < 4; m++) {
        if (nb0 + nl + m >= NN) continue;
        float4 uA = (m == 0) ? uA0 : (m == 1) ? uA1 : (m == 2) ? uA2 : uA3;
        float4 uB = (m == 0) ? uB0 : (m == 1) ? uB1 : (m == 2) ? uB2 : uB3;
        uint2 pa, pb;
        pa.x = pack_half2(uA.x, uA.y); pa.y = pack_half2(uA.z, uA.w);
        pb.x = pack_half2(uB.x, uB.y); pb.y = pack_half2(uB.z, uB.w);
        d_th1h[(nb0 + nl + m + 1) * 16 + ch] = pa;
        d_tm1h[(nb0 + nl + m + 1) * 16 + ch] = pb;
    }

    if (blockIdx.x == 0 && t < 16) {
        d_th1h[t] = make_uint2(0u, 0u);
        d_tm1h[t] = make_uint2(0u, 0u);
    }
    if (blockIdx.x == 0 && t == 0) { d_gp1[0] = 0.f; d_gm1[0] = 0.f; }
}

// ---------------- fused alpha + gather + ELU, iteration 2 (fp16 tables) ----------
__global__ __launch_bounds__(256) void k_gather2(const int* __restrict__ se,
                                                 const int* __restrict__ bs,
                                                 const int* __restrict__ su,
                                                 const int* __restrict__ sul) {
    __shared__ float4 sbc[8][2][17];
    int t = threadIdx.x, w = t >> 5, l = t & 31, sub = l & 15, half = l >> 4;
    int n = (blockIdx.x * 8 + w) * 2 + half;

    int idx = se[n * KK + sub];
    int e   = bs[n * KK + sub];
    int j   = __ldg(&su[e]);
    float msk = (__ldg(&sul[e]) > 0) ? 1.f : 0.f;
    float v = __ldg(&d_gp1[idx]) + msk * __ldg(&d_gm1[j]);
    v = (v > 0.f) ? v : 0.2f * v;
    float alpha = softmax16((idx == 0) ? NEGINF : v);

    sbc[w][half][sub] = make_float4(alpha, __int_as_float(idx), __int_as_float(j),
                                    alpha * msk);
    __syncwarp();

    float4 acc = make_float4(0.f, 0.f, 0.f, 0.f);
    #pragma unroll
    for (int k = 0; k < KK; k++) {
        float4 b = sbc[w][half][k];
        int i  = __float_as_int(b.y);
        int jj = __float_as_int(b.z);
        uint2 hv = d_th1h[i * 16 + sub];
        float2 vA = unpack_half2(hv.x), vB = unpack_half2(hv.y);
        acc.x += b.x * vA.x; acc.y += b.x * vA.y;
        acc.z += b.x * vB.x; acc.w += b.x * vB.y;
        uint2 hu = d_tm1h[jj * 16 + sub];
        float2 uA = unpack_half2(hu.x), uB = unpack_half2(hu.y);
        acc.x += b.w * uA.x; acc.y += b.w * uA.y;
        acc.z += b.w * uB.x; acc.w += b.w * uB.y;
    }
    ELU4(acc)
    uint2 pk;
    pk.x = pack_half2(acc.x, acc.y);
    pk.y = pack_half2(acc.z, acc.w);
    d_hp2h[(n + 1) * 16 + sub] = pk;
    if (blockIdx.x == 0 && t < 16) d_hp2h[t] = make_uint2(0u, 0u);
}

// ---------------- readout (fp16 hp2 -> fp32 out) ----------------------------------
__global__ __launch_bounds__(256) void k_out(const int* __restrict__ ls,
                                             float* __restrict__ out) {
    int wid = (blockIdx.x * blockDim.x + threadIdx.x) >> 5;
    int l = threadIdx.x & 31;
    int sub = l & 15;
    int mol = wid * 2 + (l >> 4);
    if (mol >= BBATCH) return;
    const int* row = ls + mol * MAXM;
    float4 acc = make_float4(0.f, 0.f, 0.f, 0.f);
    #pragma unroll 8
    for (int m = 0; m < MAXM; m++) {
        int i = __ldg(row + m);
        uint2 hv = d_hp2h[i * 16 + sub];
        float2 vA = unpack_half2(hv.x), vB = unpack_half2(hv.y);
        acc.x += vA.x; acc.y += vA.y; acc.z += vB.x; acc.w += vB.y;
    }
    ((float4*)out)[mol * 16 + sub] = acc;
}

// ---------------- launch -----------------------------------------------------------
extern "C" void kernel_launch(void* const* d_in, const int* in_sizes, int n_in,
                              void* d_out, int out_size) {
    const float* tf  = (const float*)d_in[0];
    const float* fdg = (const float*)d_in[1];
    const float* rij = (const float*)d_in[2];
    const int*   se  = (const int*)d_in[3];
    const int*   bs  = (const int*)d_in[4];
    const int*   ls  = (const int*)d_in[5];
    const int*   su  = (const int*)d_in[6];
    const int*   sul = (const int*)d_in[7];
    const float* We  = (const float*)d_in[8];
    const float* be  = (const float*)d_in[9];
    const float* Wd  = (const float*)d_in[10];
    const float* bd  = (const float*)d_in[11];
    const float* Wg  = (const float*)d_in[12];
    const float* Wm  = (const float*)d_in[13];
    const float* ag  = (const float*)d_in[14];

    // sWg 16384 + sWm 16384 + sacc 17408 + sa9 2560 + sax 2560 = 55296 B
    int mega_smem = 2048 * 16 + 64 * 68 * 4 + 64 * 10 * 4 + 64 * 10 * 4;
    static int smem_set = 0;
    if (!smem_set) {
        cudaFuncSetAttribute(k_mega, cudaFuncAttributeMaxDynamicSharedMemorySize, mega_smem);
        smem_set = 1;
    }

    int gat_blocks = NN / 16;               // 3125
    int gemm_blocks = (NN + 63) / 64;       // 782

    k_consts<<<9, 256>>>(Wg, Wm, ag, Wd, bd, We, be);
    k_pre<<<NB_G, 256>>>(tf);

    k_gather1<<<gat_blocks, 256>>>(se, bs, tf, fdg, rij);
    k_mega<<<gemm_blocks, 256, mega_smem>>>(Wg, Wm);
    k_gather2<<<gat_blocks, 256>>>(se, bs, su, sul);

    k_out<<<(BBATCH / 2 + 7) / 8, 256>>>(ls, (float*)d_out);
}